// round 3
// baseline (speedup 1.0000x reference)
#include <cuda_runtime.h>

// LSTM: B=4096, T=999, H=51 (padded to 64), INPUT=1, OUTPUT=1, future=0
// Persistent-CTA design: 128 CTAs x 32 batch rows, 512 threads.
// Thread tile: 2 rows x 2 hidden units, gates packed as f32x2 (unit pairs),
// math via fma.rn.f32x2 (FFMA2) with SMEM-broadcast weights.

#define HID   51
#define HP    64          // padded hidden
#define SEQ   999
#define CH    111         // x chunk length (999 = 9*111)
#define BT    32          // batch rows per CTA
#define NTH   512
#define WQS   256         // floats per k-row in swizzled W (HP*4 gates)
#define NBLK  128         // 4096 / 32

typedef unsigned long long u64;

__device__ __forceinline__ u64 pack2(float x, float y) {
    u64 r; asm("mov.b64 %0, {%1, %2};" : "=l"(r) : "f"(x), "f"(y)); return r;
}
__device__ __forceinline__ float2 unpack2(u64 v) {
    float2 r; asm("mov.b64 {%0, %1}, %2;" : "=f"(r.x), "=f"(r.y) : "l"(v)); return r;
}
__device__ __forceinline__ void fma2(u64& a, u64 x, u64 y) {
    asm("fma.rn.f32x2 %0, %1, %2, %0;" : "+l"(a) : "l"(x), "l"(y));
}
// sigmoid(x) = 1 / (1 + 2^(-x*log2e)); saturates cleanly at +/-inf (no NaN)
__device__ __forceinline__ float fsig(float x) {
    float e, r;
    asm("ex2.approx.f32 %0, %1;" : "=f"(e) : "f"(-1.4426950408889634f * x));
    asm("rcp.approx.f32 %0, %1;" : "=f"(r) : "f"(1.0f + e));
    return r;
}
__device__ __forceinline__ float ftanh_(float x) {
    return fmaf(2.0f, fsig(2.0f * x), -1.0f);
}

// SMEM layout (bytes):
//   h_s : float2[HP*BT]   @ 0        (64*32*8  = 16384)  h stored duplicated (h,h), [unit][row]
//   xs  : float2[CH*BT]   @ 16384    (111*32*8 = 28416)  x stored duplicated, [t][row]
//   Wq  : float [HID*WQS] @ 44800    (51*256*4 = 52224)  [k][pair(32)][gate(4)][j(2)]
//   wfc : float [52]      @ 97024
#define SM_H   0
#define SM_X   16384
#define SM_W   44800
#define SM_FC  97024
#define SM_TOT 97280

extern "C" __global__ void __launch_bounds__(NTH, 1)
lstm_kernel(const float* __restrict__ x,    // (B, SEQ)
            const float* __restrict__ Wih,  // (204, 1)
            const float* __restrict__ Whh,  // (204, 51)
            const float* __restrict__ bih,  // (204)
            const float* __restrict__ bhh,  // (204)
            const float* __restrict__ Wfc,  // (1, 51)
            const float* __restrict__ bfc,  // (1)
            float* __restrict__ out)        // (B, SEQ)
{
    extern __shared__ char smem[];
    float2* h_s = (float2*)(smem + SM_H);
    float2* xs  = (float2*)(smem + SM_X);
    float*  Wq  = (float*) (smem + SM_W);
    float*  wfc = (float*) (smem + SM_FC);

    const int tid  = threadIdx.x;
    const int rg   = tid & 15;   // row-pair group: rows 2rg, 2rg+1
    const int ug   = tid >> 4;   // unit-pair group: units 2ug, 2ug+1 (0..31)
    const int row0 = blockIdx.x * BT;

    // ---- one-time SMEM fills ----
    // Swizzled recurrent weights: Wq[k*256 + p*8 + gate*2 + j] = Whh[(gate*51 + 2p+j)][k]
    for (int idx = tid; idx < HID * WQS; idx += NTH) {
        int k = idx >> 8, rem = idx & 255;
        int p = rem >> 3, gate = (rem >> 1) & 3, j = rem & 1;
        int u = 2 * p + j;
        Wq[idx] = (u < HID) ? Whh[(gate * HID + u) * HID + k] : 0.0f;
    }
    for (int idx = tid; idx < HID; idx += NTH) wfc[idx] = Wfc[idx];
    for (int idx = tid; idx < HP * BT; idx += NTH) h_s[idx] = make_float2(0.f, 0.f);

    // Per-thread gate bias (b_ih + b_hh) and W_ih, packed per unit pair
    const int u0 = 2 * ug, u1 = 2 * ug + 1;
    u64 Bq[4], Wi[4];
#pragma unroll
    for (int gate = 0; gate < 4; gate++) {
        float b0 = 0.f, b1 = 0.f, w0 = 0.f, w1 = 0.f;
        if (u0 < HID) { int g = gate * HID + u0; b0 = bih[g] + bhh[g]; w0 = Wih[g]; }
        if (u1 < HID) { int g = gate * HID + u1; b1 = bih[g] + bhh[g]; w1 = Wih[g]; }
        Bq[gate] = pack2(b0, b1);
        Wi[gate] = pack2(w0, w1);
    }
    float c00 = 0.f, c01 = 0.f, c10 = 0.f, c11 = 0.f;  // c[row r][unit j]
    const float bfc_v = bfc[0];

    const float*  wq_base = Wq + (ug << 3);
    const float2* h_rd    = h_s + (rg << 1);

    __syncthreads();

    for (int t = 0; t < SEQ; t++) {
        const int tt = t % CH;
        if (tt == 0) {
            // refill x chunk (coalesced in t); all old xs reads finished before prev syncB
            for (int idx = tid; idx < BT * CH; idx += NTH) {
                int r = idx / CH;
                int s = idx - r * CH;
                float v = x[(row0 + r) * SEQ + t + s];
                xs[s * BT + r] = make_float2(v, v);
            }
            __syncthreads();
        }

        // init gate accumulators: bias + x * W_ih
        ulonglong2 xv = *(const ulonglong2*)(xs + tt * BT + (rg << 1));
        u64 ai0 = Bq[0], af0 = Bq[1], ag0 = Bq[2], ao0 = Bq[3];
        u64 ai1 = Bq[0], af1 = Bq[1], ag1 = Bq[2], ao1 = Bq[3];
        fma2(ai0, xv.x, Wi[0]); fma2(af0, xv.x, Wi[1]);
        fma2(ag0, xv.x, Wi[2]); fma2(ao0, xv.x, Wi[3]);
        fma2(ai1, xv.y, Wi[0]); fma2(af1, xv.y, Wi[1]);
        fma2(ag1, xv.y, Wi[2]); fma2(ao1, xv.y, Wi[3]);

        // recurrent GEMM fragment: 51 k-steps, 3 LDS.128 + 8 FFMA2 each
#pragma unroll
        for (int k = 0; k < HID; k++) {
            ulonglong2 wA = *(const ulonglong2*)(wq_base + (k << 8));      // (i-pair, f-pair)
            ulonglong2 wB = *(const ulonglong2*)(wq_base + (k << 8) + 4);  // (g-pair, o-pair)
            ulonglong2 hv = *(const ulonglong2*)(h_rd + k * BT);           // (h_r0 dup, h_r1 dup)
            fma2(ai0, hv.x, wA.x); fma2(af0, hv.x, wA.y);
            fma2(ag0, hv.x, wB.x); fma2(ao0, hv.x, wB.y);
            fma2(ai1, hv.y, wA.x); fma2(af1, hv.y, wA.y);
            fma2(ag1, hv.y, wB.x); fma2(ao1, hv.y, wB.y);
        }

        // elementwise LSTM cell update (fp32, accurate MUFU path)
        float2 gi0 = unpack2(ai0), gf0 = unpack2(af0), gg0 = unpack2(ag0), go0 = unpack2(ao0);
        float2 gi1 = unpack2(ai1), gf1 = unpack2(af1), gg1 = unpack2(ag1), go1 = unpack2(ao1);

        c00 = fsig(gf0.x) * c00 + fsig(gi0.x) * ftanh_(gg0.x);
        float h00 = fsig(go0.x) * ftanh_(c00);
        c01 = fsig(gf0.y) * c01 + fsig(gi0.y) * ftanh_(gg0.y);
        float h01 = fsig(go0.y) * ftanh_(c01);
        c10 = fsig(gf1.x) * c10 + fsig(gi1.x) * ftanh_(gg1.x);
        float h10 = fsig(go1.x) * ftanh_(c10);
        c11 = fsig(gf1.y) * c11 + fsig(gi1.y) * ftanh_(gg1.y);
        float h11 = fsig(go1.y) * ftanh_(c11);

        __syncthreads();  // A: all reads of old h done

        const int r0i = rg << 1, r1i = r0i + 1;
        h_s[u0 * BT + r0i] = make_float2(h00, h00);
        h_s[u1 * BT + r0i] = make_float2(h01, h01);
        h_s[u0 * BT + r1i] = make_float2(h10, h10);
        h_s[u1 * BT + r1i] = make_float2(h11, h11);

        __syncthreads();  // B: new h visible

        // per-step FC output: y[r] = b_fc + sum_u wfc[u] * h[u][r]   (warp 0, lane = row)
        if (tid < BT) {
            float a0 = bfc_v, a1 = 0.f, a2 = 0.f;
#pragma unroll
            for (int u = 0; u < HID; u += 3) {
                a0 += wfc[u]     * h_s[u * BT + tid].x;
                a1 += wfc[u + 1] * h_s[(u + 1) * BT + tid].x;
                a2 += wfc[u + 2] * h_s[(u + 2) * BT + tid].x;
            }
            out[(row0 + tid) * SEQ + t] = a0 + a1 + a2;
        }
    }
}

extern "C" void kernel_launch(void* const* d_in, const int* in_sizes, int n_in,
                              void* d_out, int out_size) {
    const float* x    = (const float*)d_in[0];
    const float* Wih  = (const float*)d_in[1];
    const float* Whh  = (const float*)d_in[2];
    const float* bihp = (const float*)d_in[3];
    const float* bhhp = (const float*)d_in[4];
    const float* Wfc  = (const float*)d_in[5];
    const float* bfcp = (const float*)d_in[6];
    // d_in[7] = future (static 0) — ignored
    float* out = (float*)d_out;

    cudaFuncSetAttribute(lstm_kernel, cudaFuncAttributeMaxDynamicSharedMemorySize, SM_TOT);
    lstm_kernel<<<NBLK, NTH, SM_TOT>>>(x, Wih, Whh, bihp, bhhp, Wfc, bfcp, out);
}

// round 4
// speedup vs baseline: 1.0190x; 1.0190x over previous
#include <cuda_runtime.h>

// LSTM: B=4096, T=999, H=51 (padded to 64), INPUT=1, OUTPUT=1, future=0
// R4 design: 256 CTAs x 16 batch rows, 256 threads, 2 CTAs/SM.
// Thread tile: 2 rows x 2 units, f32x2 FFMA2, double-buffered h, 1 barrier/step.

#define HID   51
#define HP    64          // padded hidden
#define SEQ   999
#define CH    111         // x chunk length (999 = 9*111)
#define BT    16          // batch rows per CTA
#define NTH   256
#define WQS   256         // floats per k-row in swizzled W (HP*4 gates)
#define NBLK  256         // 4096 / 16
#define HPBT  (HP*BT)     // float2 elems per h buffer (1024)

typedef unsigned long long u64;

__device__ __forceinline__ u64 pack2(float x, float y) {
    u64 r; asm("mov.b64 %0, {%1, %2};" : "=l"(r) : "f"(x), "f"(y)); return r;
}
__device__ __forceinline__ float2 unpack2(u64 v) {
    float2 r; asm("mov.b64 {%0, %1}, %2;" : "=f"(r.x), "=f"(r.y) : "l"(v)); return r;
}
__device__ __forceinline__ void fma2(u64& a, u64 x, u64 y) {
    asm("fma.rn.f32x2 %0, %1, %2, %0;" : "+l"(a) : "l"(x), "l"(y));
}
// sigmoid(x) = 1 / (1 + 2^(-x*log2e)); accurate MUFU path, saturates cleanly
__device__ __forceinline__ float fsig(float x) {
    float e, r;
    asm("ex2.approx.f32 %0, %1;" : "=f"(e) : "f"(-1.4426950408889634f * x));
    asm("rcp.approx.f32 %0, %1;" : "=f"(r) : "f"(1.0f + e));
    return r;
}
__device__ __forceinline__ float ftanh_(float x) {
    return fmaf(2.0f, fsig(2.0f * x), -1.0f);
}

// SMEM layout (bytes):
//   h_s : float2[2][HP*BT] @ 0      (2*64*16*8 = 16384) h dup (h,h), [buf][unit][row]
//   xs  : float [CH*BT]    @ 16384  (111*16*4  = 7104)
//   Wq  : float [HID*WQS]  @ 23488  (51*256*4  = 52224) [k][pair(32)][gate(4)][j(2)]
//   wfc : float [64]       @ 75712
#define SM_H   0
#define SM_X   16384
#define SM_W   23488
#define SM_FC  75712
#define SM_TOT 75968

extern "C" __global__ void __launch_bounds__(NTH, 2)
lstm_kernel(const float* __restrict__ x,    // (B, SEQ)
            const float* __restrict__ Wih,  // (204, 1)
            const float* __restrict__ Whh,  // (204, 51)
            const float* __restrict__ bih,  // (204)
            const float* __restrict__ bhh,  // (204)
            const float* __restrict__ Wfc,  // (1, 51)
            const float* __restrict__ bfc,  // (1)
            float* __restrict__ out)        // (B, SEQ)
{
    extern __shared__ char smem[];
    float2* h_s = (float2*)(smem + SM_H);
    float*  xs  = (float*) (smem + SM_X);
    float*  Wq  = (float*) (smem + SM_W);
    float*  wfc = (float*) (smem + SM_FC);

    const int tid  = threadIdx.x;
    const int rg   = tid & 7;    // row-pair group: rows 2rg, 2rg+1 (0..15)
    const int ug   = tid >> 3;   // unit-pair group: units 2ug, 2ug+1 (0..31)
    const int row0 = blockIdx.x * BT;

    // ---- one-time SMEM fills ----
    // Wq[k*256 + p*8 + gate*2 + j] = Whh[(gate*51 + 2p+j)][k], zero-padded
    for (int idx = tid; idx < HID * WQS; idx += NTH) {
        int k = idx >> 8, rem = idx & 255;
        int p = rem >> 3, gate = (rem >> 1) & 3, j = rem & 1;
        int u = 2 * p + j;
        Wq[idx] = (u < HID) ? Whh[(gate * HID + u) * HID + k] : 0.0f;
    }
    for (int idx = tid; idx < HID; idx += NTH) wfc[idx] = Wfc[idx];
    for (int idx = tid; idx < 2 * HPBT; idx += NTH) h_s[idx] = make_float2(0.f, 0.f);

    // Per-thread gate bias (b_ih + b_hh) and W_ih, packed per unit pair
    const int u0 = 2 * ug, u1 = 2 * ug + 1;
    u64 Bq[4], Wi[4];
#pragma unroll
    for (int gate = 0; gate < 4; gate++) {
        float b0 = 0.f, b1 = 0.f, w0 = 0.f, w1 = 0.f;
        if (u0 < HID) { int g = gate * HID + u0; b0 = bih[g] + bhh[g]; w0 = Wih[g]; }
        if (u1 < HID) { int g = gate * HID + u1; b1 = bih[g] + bhh[g]; w1 = Wih[g]; }
        Bq[gate] = pack2(b0, b1);
        Wi[gate] = pack2(w0, w1);
    }
    float c00 = 0.f, c01 = 0.f, c10 = 0.f, c11 = 0.f;  // c[row r][unit j]
    const float bfc_v = bfc[0];

    const float* wq_base = Wq + (ug << 3);

    __syncthreads();

    for (int t = 0; t < SEQ; t++) {
        const int tt = t % CH;
        if (tt == 0) {
            // refill x chunk; previous xs reads completed before last step barrier
            for (int idx = tid; idx < BT * CH; idx += NTH) {
                int r = idx / CH;
                int s = idx - r * CH;
                xs[s * BT + r] = x[(row0 + r) * SEQ + t + s];
            }
            __syncthreads();
        }

        const float2* h_rd = h_s + (t & 1) * HPBT + (rg << 1);
        float2*       h_wr = h_s + ((t + 1) & 1) * HPBT;

        // init gate accumulators: bias + x * W_ih
        float2 xr = *(const float2*)(xs + tt * BT + (rg << 1));
        u64 xv0 = pack2(xr.x, xr.x), xv1 = pack2(xr.y, xr.y);
        u64 ai0 = Bq[0], af0 = Bq[1], ag0 = Bq[2], ao0 = Bq[3];
        u64 ai1 = Bq[0], af1 = Bq[1], ag1 = Bq[2], ao1 = Bq[3];
        fma2(ai0, xv0, Wi[0]); fma2(af0, xv0, Wi[1]);
        fma2(ag0, xv0, Wi[2]); fma2(ao0, xv0, Wi[3]);
        fma2(ai1, xv1, Wi[0]); fma2(af1, xv1, Wi[1]);
        fma2(ag1, xv1, Wi[2]); fma2(ao1, xv1, Wi[3]);

        // recurrent GEMM fragment: 51 k-steps, 3 LDS.128 + 8 FFMA2 each
#pragma unroll
        for (int k = 0; k < HID; k++) {
            ulonglong2 wA = *(const ulonglong2*)(wq_base + (k << 8));      // (i-pair, f-pair)
            ulonglong2 wB = *(const ulonglong2*)(wq_base + (k << 8) + 4);  // (g-pair, o-pair)
            ulonglong2 hv = *(const ulonglong2*)(h_rd + k * BT);           // (h_r0 dup, h_r1 dup)
            fma2(ai0, hv.x, wA.x); fma2(af0, hv.x, wA.y);
            fma2(ag0, hv.x, wB.x); fma2(ao0, hv.x, wB.y);
            fma2(ai1, hv.y, wA.x); fma2(af1, hv.y, wA.y);
            fma2(ag1, hv.y, wB.x); fma2(ao1, hv.y, wB.y);
        }

        // elementwise LSTM cell update (fp32, accurate MUFU path)
        float2 gi0 = unpack2(ai0), gf0 = unpack2(af0), gg0 = unpack2(ag0), go0 = unpack2(ao0);
        float2 gi1 = unpack2(ai1), gf1 = unpack2(af1), gg1 = unpack2(ag1), go1 = unpack2(ao1);

        c00 = fsig(gf0.x) * c00 + fsig(gi0.x) * ftanh_(gg0.x);
        float h00 = fsig(go0.x) * ftanh_(c00);
        c01 = fsig(gf0.y) * c01 + fsig(gi0.y) * ftanh_(gg0.y);
        float h01 = fsig(go0.y) * ftanh_(c01);
        c10 = fsig(gf1.x) * c10 + fsig(gi1.x) * ftanh_(gg1.x);
        float h10 = fsig(go1.x) * ftanh_(c10);
        c11 = fsig(gf1.y) * c11 + fsig(gi1.y) * ftanh_(gg1.y);
        float h11 = fsig(go1.y) * ftanh_(c11);

        // store into write buffer (no hazard with read buffer)
        const int r0i = rg << 1, r1i = r0i + 1;
        h_wr[u0 * BT + r0i] = make_float2(h00, h00);
        h_wr[u1 * BT + r0i] = make_float2(h01, h01);
        h_wr[u0 * BT + r1i] = make_float2(h10, h10);
        h_wr[u1 * BT + r1i] = make_float2(h11, h11);

        __syncthreads();  // new h visible; old-buffer reads all retired

        // per-step FC output: y[r] = b_fc + sum_u wfc[u] * h[u][r]  (16 lanes of warp 0)
        // overlaps next step's GEMM: next step writes the OTHER buffer.
        if (tid < BT) {
            float a0 = bfc_v, a1 = 0.f, a2 = 0.f;
#pragma unroll
            for (int u = 0; u < HID; u += 3) {
                a0 += wfc[u]     * h_wr[u * BT + tid].x;
                a1 += wfc[u + 1] * h_wr[(u + 1) * BT + tid].x;
                a2 += wfc[u + 2] * h_wr[(u + 2) * BT + tid].x;
            }
            out[(row0 + tid) * SEQ + t] = a0 + a1 + a2;
        }
    }
}

extern "C" void kernel_launch(void* const* d_in, const int* in_sizes, int n_in,
                              void* d_out, int out_size) {
    const float* x    = (const float*)d_in[0];
    const float* Wih  = (const float*)d_in[1];
    const float* Whh  = (const float*)d_in[2];
    const float* bihp = (const float*)d_in[3];
    const float* bhhp = (const float*)d_in[4];
    const float* Wfc  = (const float*)d_in[5];
    const float* bfcp = (const float*)d_in[6];
    // d_in[7] = future (static 0) — ignored
    float* out = (float*)d_out;

    cudaFuncSetAttribute(lstm_kernel, cudaFuncAttributeMaxDynamicSharedMemorySize, SM_TOT);
    lstm_kernel<<<NBLK, NTH, SM_TOT>>>(x, Wih, Whh, bihp, bhhp, Wfc, bfcp, out);
}

// round 5
// speedup vs baseline: 1.2406x; 1.2175x over previous
#include <cuda_runtime.h>

// LSTM B=4096, T=999, H=51(pad 64), I=1, O=1.
// R5: warp-pair autonomy. CTA=256 thr (8 warps = 4 pairs). Pair owns 8 batch
// rows; warp half owns 32 units. No __syncthreads in loop — only per-pair
// named barriers, so pairs desync and pipes overlap. f32x2 FFMA2 GEMM.

#define HID   51
#define SEQ   999
#define CH    111        // 999 = 9*111
#define NTH   256
#define NBLK  128        // 128 CTAs * 32 rows = 4096

typedef unsigned long long u64;

__device__ __forceinline__ u64 pack2(float x, float y) {
    u64 r; asm("mov.b64 %0, {%1, %2};" : "=l"(r) : "f"(x), "f"(y)); return r;
}
__device__ __forceinline__ float2 unpack2(u64 v) {
    float2 r; asm("mov.b64 {%0, %1}, %2;" : "=f"(r.x), "=f"(r.y) : "l"(v)); return r;
}
__device__ __forceinline__ void fma2(u64& a, u64 x, u64 y) {
    asm("fma.rn.f32x2 %0, %1, %2, %0;" : "+l"(a) : "l"(x), "l"(y));
}
__device__ __forceinline__ float fsig(float x) {          // accurate MUFU sigmoid
    float e, r;
    asm("ex2.approx.f32 %0, %1;" : "=f"(e) : "f"(-1.4426950408889634f * x));
    asm("rcp.approx.f32 %0, %1;" : "=f"(r) : "f"(1.0f + e));
    return r;
}
__device__ __forceinline__ float ftanh_(float x) { return fmaf(2.0f, fsig(2.0f * x), -1.0f); }

// SMEM (bytes):
//  hP : 4 pairs * [64 units][10 rows-slots] float2 dup   = 4*5120  = 20480 @ 0
//  xW : 8 warps * [111 t][8 rows] float                  = 8*3552  = 28416 @ 20480
//  Wq : [51 k][2 blk][32 pair][4] float (gate-blocked)   = 52224            @ 48896
//  wfc: 64 float                                                            @ 101120
#define SM_H   0
#define SM_X   20480
#define SM_W   48896
#define SM_FC  101120
#define SM_TOT 101376

extern "C" __global__ void __launch_bounds__(NTH, 1)
lstm_kernel(const float* __restrict__ x,    // (B, SEQ)
            const float* __restrict__ Wih,  // (204, 1)
            const float* __restrict__ Whh,  // (204, 51)
            const float* __restrict__ bih,  // (204)
            const float* __restrict__ bhh,  // (204)
            const float* __restrict__ Wfc,  // (1, 51)
            const float* __restrict__ bfc,  // (1)
            float* __restrict__ out)        // (B, SEQ)
{
    extern __shared__ char smem[];
    const int tid  = threadIdx.x;
    const int w    = tid >> 5;       // warp 0..7
    const int l    = tid & 31;
    const int pair = w >> 1;         // 0..3 ; pair owns rows pair*8..+7
    const int half = w & 1;          // unit half: 0 -> units 0..31, 1 -> 32..63
    const int pr   = l & 15;         // unit-pair within half
    const int rowq = l >> 4;         // lanes 0-15: rows 0-3 ; 16-31: rows 4-7
    const int U0   = half * 32 + 2 * pr, U1 = U0 + 1;
    const int row0 = blockIdx.x * 32 + pair * 8;   // global base row of the pair

    float* hP  = (float*)(smem + SM_H) + pair * 1280;  // (u,r) at u*20 + r*2 floats
    float* xW  = (float*)(smem + SM_X) + w * 888;      // (s,r) at s*8 + r
    float* Wq  = (float*)(smem + SM_W);
    float* wfc = (float*)(smem + SM_FC);

    // ---- one-time init ----
    // Wq[k*256 + blk*128 + p*4 + e]: blk0 -> gates(i,f), blk1 -> gates(g,o)
    // e: {gA[u0], gA[u1], gB[u0], gB[u1]}, u = 2p + (e&1)
    for (int idx = tid; idx < HID * 256; idx += NTH) {
        int k = idx >> 8, rem = idx & 255;
        int b = rem >> 7, p = (rem >> 2) & 31, e = rem & 3;
        int gate = b * 2 + (e >> 1);
        int u = 2 * p + (e & 1);
        Wq[idx] = (u < HID) ? Whh[(gate * HID + u) * HID + k] : 0.0f;
    }
    for (int idx = tid; idx < 64; idx += NTH) wfc[idx] = (idx < HID) ? Wfc[idx] : 0.0f;
    for (int idx = tid; idx < 4 * 1280; idx += NTH) ((float*)(smem + SM_H))[idx] = 0.0f;

    u64 Bq[4], Wi[4];
#pragma unroll
    for (int g = 0; g < 4; g++) {
        float b0 = 0.f, b1 = 0.f, w0 = 0.f, w1 = 0.f;
        if (U0 < HID) { int i = g * HID + U0; b0 = bih[i] + bhh[i]; w0 = Wih[i]; }
        if (U1 < HID) { int i = g * HID + U1; b1 = bih[i] + bhh[i]; w1 = Wih[i]; }
        Bq[g] = pack2(b0, b1);
        Wi[g] = pack2(w0, w1);
    }
    float cst[8];                       // c[r][j], r=0..3 (lane's 4 rows), j=unit 0/1
#pragma unroll
    for (int i = 0; i < 8; i++) cst[i] = 0.f;
    const float bfc_v = bfc[0];

    const float* wqA = Wq + ((half * 16 + pr) << 2);   // + k*256 (+128 for blk1)
    const float* hRd = hP + (rowq << 3);               // + k*20
    const int    bid = pair + 1;                       // named barrier id

    __syncthreads();                                   // init visible

    for (int t = 0; t < SEQ; t++) {
        const int tt = t % CH;
        if (tt == 0) {
            // warp-private x refill: 8 rows x CH, coalesced LDG
#pragma unroll
            for (int r = 0; r < 8; r++) {
                const float* xr = x + (row0 + r) * SEQ + t;
                for (int s = l; s < CH; s += 32) xW[s * 8 + r] = xr[s];
            }
            __syncwarp();
        }

        // gate init: bias + x * W_ih   (4 rows)
        float4 xv = *(const float4*)(xW + tt * 8 + rowq * 4);
        u64 xd0 = pack2(xv.x, xv.x), xd1 = pack2(xv.y, xv.y);
        u64 xd2 = pack2(xv.z, xv.z), xd3 = pack2(xv.w, xv.w);
        u64 ai0 = Bq[0], af0 = Bq[1], ag0 = Bq[2], ao0 = Bq[3];
        u64 ai1 = Bq[0], af1 = Bq[1], ag1 = Bq[2], ao1 = Bq[3];
        u64 ai2 = Bq[0], af2 = Bq[1], ag2 = Bq[2], ao2 = Bq[3];
        u64 ai3 = Bq[0], af3 = Bq[1], ag3 = Bq[2], ao3 = Bq[3];
        fma2(ai0, xd0, Wi[0]); fma2(af0, xd0, Wi[1]); fma2(ag0, xd0, Wi[2]); fma2(ao0, xd0, Wi[3]);
        fma2(ai1, xd1, Wi[0]); fma2(af1, xd1, Wi[1]); fma2(ag1, xd1, Wi[2]); fma2(ao1, xd1, Wi[3]);
        fma2(ai2, xd2, Wi[0]); fma2(af2, xd2, Wi[1]); fma2(ag2, xd2, Wi[2]); fma2(ao2, xd2, Wi[3]);
        fma2(ai3, xd3, Wi[0]); fma2(af3, xd3, Wi[1]); fma2(ag3, xd3, Wi[2]); fma2(ao3, xd3, Wi[3]);

        // recurrent GEMM: 51 k-steps, 4 LDS.128 + 16 FFMA2 each
#pragma unroll
        for (int k = 0; k < HID; k++) {
            ulonglong2 wA  = *(const ulonglong2*)(wqA + (k << 8));        // (i-pair, f-pair)
            ulonglong2 wB  = *(const ulonglong2*)(wqA + (k << 8) + 128);  // (g-pair, o-pair)
            ulonglong2 h01 = *(const ulonglong2*)(hRd + k * 20);          // rows 0,1 dup
            ulonglong2 h23 = *(const ulonglong2*)(hRd + k * 20 + 4);      // rows 2,3 dup
            fma2(ai0, h01.x, wA.x); fma2(af0, h01.x, wA.y); fma2(ag0, h01.x, wB.x); fma2(ao0, h01.x, wB.y);
            fma2(ai1, h01.y, wA.x); fma2(af1, h01.y, wA.y); fma2(ag1, h01.y, wB.x); fma2(ao1, h01.y, wB.y);
            fma2(ai2, h23.x, wA.x); fma2(af2, h23.x, wA.y); fma2(ag2, h23.x, wB.x); fma2(ao2, h23.x, wB.y);
            fma2(ai3, h23.y, wA.x); fma2(af3, h23.y, wA.y); fma2(ag3, h23.y, wB.x); fma2(ao3, h23.y, wB.y);
        }

        // elementwise cell update (register-only)
        float ho[8];
        {
            float2 gi, gf, gg, go;
#define CELL(R, AI, AF, AG, AO)                                              \
            gi = unpack2(AI); gf = unpack2(AF); gg = unpack2(AG); go = unpack2(AO); \
            cst[R*2]   = fsig(gf.x) * cst[R*2]   + fsig(gi.x) * ftanh_(gg.x);       \
            ho[R*2]    = fsig(go.x) * ftanh_(cst[R*2]);                             \
            cst[R*2+1] = fsig(gf.y) * cst[R*2+1] + fsig(gi.y) * ftanh_(gg.y);       \
            ho[R*2+1]  = fsig(go.y) * ftanh_(cst[R*2+1]);
            CELL(0, ai0, af0, ag0, ao0)
            CELL(1, ai1, af1, ag1, ao1)
            CELL(2, ai2, af2, ag2, ao2)
            CELL(3, ai3, af3, ag3, ao3)
#undef CELL
        }

        asm volatile("bar.sync %0, %1;" :: "r"(bid), "r"(64) : "memory");  // A: old-h reads done

        // store new h (dup) : units U0,U1 x 4 rows
        {
            const int rb = rowq << 2;
#pragma unroll
            for (int r = 0; r < 4; r++) {
                *(float2*)(hP + U0 * 20 + ((rb + r) << 1)) = make_float2(ho[r*2],   ho[r*2]);
                *(float2*)(hP + U1 * 20 + ((rb + r) << 1)) = make_float2(ho[r*2+1], ho[r*2+1]);
            }
        }

        asm volatile("bar.sync %0, %1;" :: "r"(bid), "r"(64) : "memory");  // B: new h visible

        // FC: warp half covers 4 rows; 8 lanes per row sum 8 units each
        {
            const int frow = half * 4 + (l >> 3);          // pair-local row
            const float* hc = hP + (frow << 1);
            const int a = l & 7;
            float s = 0.f;
#pragma unroll
            for (int j = 0; j < 8; j++) {
                int u = a + (j << 3);
                s += wfc[u] * hc[u * 20];                  // h pad rows are 0
            }
            s += __shfl_xor_sync(0xffffffffu, s, 1);
            s += __shfl_xor_sync(0xffffffffu, s, 2);
            s += __shfl_xor_sync(0xffffffffu, s, 4);
            if (a == 0) out[(row0 + frow) * SEQ + t] = s + bfc_v;
        }
    }
}

extern "C" void kernel_launch(void* const* d_in, const int* in_sizes, int n_in,
                              void* d_out, int out_size) {
    const float* x    = (const float*)d_in[0];
    const float* Wih  = (const float*)d_in[1];
    const float* Whh  = (const float*)d_in[2];
    const float* bihp = (const float*)d_in[3];
    const float* bhhp = (const float*)d_in[4];
    const float* Wfc  = (const float*)d_in[5];
    const float* bfcp = (const float*)d_in[6];
    // d_in[7] = future (static 0) — ignored
    float* out = (float*)d_out;

    cudaFuncSetAttribute(lstm_kernel, cudaFuncAttributeMaxDynamicSharedMemorySize, SM_TOT);
    lstm_kernel<<<NBLK, NTH, SM_TOT>>>(x, Wih, Whh, bihp, bhhp, Wfc, bfcp, out);
}